// round 11
// baseline (speedup 1.0000x reference)
#include <cuda_runtime.h>
#include <cuda_bf16.h>
#include <math.h>

// Problem constants
constexpr int B_   = 16;
constexpr int C_   = 512;
constexpr int MID_ = 256;
constexpr int N_   = 2048;
constexpr float EPS_ = 1e-5f;

// MMA tiling (proj/out kernels)
constexpr int TBM = 128;
constexpr int TBN = 128;
constexpr int TBK = 32;
constexpr int TSTR = 40;   // bf16 row stride (80B), ldmatrix conflict-free

// Flash attn tiling
constexpr int JT = 64;     // j rows per block
constexpr int IT = 64;     // i per iteration
constexpr int KC = 32;     // k chunk for S GEMM
constexpr int VSTR = 72;   // stride for P/V tiles (144B rows, 16B-aligned, ldsm conflict-free)

typedef __nv_bfloat16 bf16;
typedef __nv_bfloat162 bf162;

// Scratch
__device__ bf16 g_qT[(size_t)B_ * N_ * MID_];   // q^T: [b][n][mid]
__device__ bf16 g_kT[(size_t)B_ * N_ * MID_];   // k^T: [b][n][mid]
__device__ bf16 g_v [(size_t)B_ * MID_ * N_];   // v:   [b][mid][n]
__device__ bf16 g_ctxT[(size_t)B_ * N_ * MID_]; // ctx^T: [b][n][mid]

__device__ __forceinline__ unsigned pack2(float lo, float hi) {
    bf162 h = __floats2bfloat162_rn(lo, hi);
    return *reinterpret_cast<unsigned*>(&h);
}

__device__ __forceinline__ void mma_bf16(float c[4], const unsigned a[4], const unsigned b[2])
{
    asm volatile(
        "mma.sync.aligned.m16n8k16.row.col.f32.bf16.bf16.f32 "
        "{%0,%1,%2,%3}, {%4,%5,%6,%7}, {%8,%9}, {%0,%1,%2,%3};\n"
        : "+f"(c[0]), "+f"(c[1]), "+f"(c[2]), "+f"(c[3])
        : "r"(a[0]), "r"(a[1]), "r"(a[2]), "r"(a[3]),
          "r"(b[0]), "r"(b[1]));
}

__device__ __forceinline__ void ldsm_x4(unsigned r[4], const bf16* p)
{
    unsigned addr = (unsigned)__cvta_generic_to_shared(p);
    asm volatile(
        "ldmatrix.sync.aligned.m8n8.x4.shared.b16 {%0,%1,%2,%3}, [%4];\n"
        : "=r"(r[0]), "=r"(r[1]), "=r"(r[2]), "=r"(r[3]) : "r"(addr));
}

// Shared k-loop step over one TBK=32 tile pair (proj/out kernels).
__device__ __forceinline__ void mma_tile(const bf16* TA, const bf16* TB,
                                         float acc[4][4][4],
                                         int wm, int wn, int lane)
{
    const int arow = (lane & 15);
    const int akof = (lane >> 4) << 3;
    const int bcol = (lane & 7) + ((lane >> 4) << 3);
    const int bkof = (lane & 8);

    #pragma unroll
    for (int ks = 0; ks < 2; ks++) {
        const int kb = ks * 16;
        unsigned af[4][4], bfr[4][2];
        #pragma unroll
        for (int mt = 0; mt < 4; mt++) {
            int row = wm * 64 + mt * 16 + arow;
            ldsm_x4(af[mt], &TA[row * TSTR + kb + akof]);
        }
        #pragma unroll
        for (int np = 0; np < 2; np++) {
            unsigned r4[4];
            int col = wn * 32 + np * 16 + bcol;
            ldsm_x4(r4, &TB[col * TSTR + kb + bkof]);
            bfr[np * 2][0]     = r4[0];
            bfr[np * 2][1]     = r4[1];
            bfr[np * 2 + 1][0] = r4[2];
            bfr[np * 2 + 1][1] = r4[3];
        }
        #pragma unroll
        for (int mt = 0; mt < 4; mt++)
            #pragma unroll
            for (int nt = 0; nt < 4; nt++)
                mma_bf16(acc[mt][nt], af[mt], bfr[nt]);
    }
}

__device__ __forceinline__ void stage_bf16(bf16* T, const bf16* src, size_t gstride,
                                           int k0, int tid)
{
    #pragma unroll
    for (int r = 0; r < 2; r++) {
        int f = tid + r * 256;
        int row = f >> 2, k8 = (f & 3) * 8;
        *reinterpret_cast<uint4*>(&T[row * TSTR + k8]) =
            *reinterpret_cast<const uint4*>(&src[(size_t)row * gstride + k0 + k8]);
    }
}

__device__ __forceinline__ void stage_f32(bf16* T, const float* src, size_t gstride,
                                          int k0, int tid)
{
    #pragma unroll
    for (int r = 0; r < 4; r++) {
        int f = tid + r * 256;
        int row = f >> 3, k4 = (f & 7) * 4;
        float4 w4 = *reinterpret_cast<const float4*>(&src[(size_t)row * gstride + k0 + k4]);
        uint2 p;
        p.x = pack2(w4.x, w4.y);
        p.y = pack2(w4.z, w4.w);
        *reinterpret_cast<uint2*>(&T[row * TSTR + k4]) = p;
    }
}

__device__ __forceinline__ void stage_xT(bf16* T, const float* xb, int k0, int n0, int tid)
{
    #pragma unroll
    for (int r = 0; r < 16; r++) {
        int f = tid + r * 256;
        int c = f >> 7, n = f & 127;
        T[n * TSTR + c] = __float2bfloat16(xb[(size_t)(k0 + c) * N_ + n0 + n]);
    }
}

// ---------------------------------------------------------------------------
// projT: q/k projection, transposed output. grid (MID/128, N/128, 2B), 256 thr.
// ---------------------------------------------------------------------------
__global__ __launch_bounds__(256, 2) void projT_mma(
    const float* __restrict__ x,
    const float* __restrict__ wq, const float* __restrict__ bq,
    const float* __restrict__ gq, const float* __restrict__ betaq,
    const float* __restrict__ mq, const float* __restrict__ vq,
    const float* __restrict__ wk, const float* __restrict__ bk,
    const float* __restrict__ gk, const float* __restrict__ betak,
    const float* __restrict__ mk, const float* __restrict__ vk)
{
    __shared__ __align__(16) bf16 As[2][TBM * TSTR];
    __shared__ __align__(16) bf16 Bs[2][TBM * TSTR];

    const int mat = blockIdx.z / B_;
    const int b   = blockIdx.z % B_;
    const int n0  = blockIdx.y * TBM;
    const int c0  = blockIdx.x * TBN;
    const int tid  = threadIdx.x;
    const int lane = tid & 31, wid = tid >> 5;
    const int wm = wid & 1, wn = wid >> 1;
    const int g = lane >> 2, tg = lane & 3;

    const float* w  = (mat == 0) ? wq : wk;
    const float* xb = x + (size_t)b * C_ * N_;

    float acc[4][4][4] = {};

    stage_xT(As[0], xb, 0, n0, tid);
    stage_f32(Bs[0], w + (size_t)c0 * C_, C_, 0, tid);
    __syncthreads();

    for (int k0 = 0; k0 < C_; k0 += TBK) {
        const int buf = (k0 / TBK) & 1;
        if (k0 + TBK < C_) {
            stage_xT(As[buf ^ 1], xb, k0 + TBK, n0, tid);
            stage_f32(Bs[buf ^ 1], w + (size_t)c0 * C_, C_, k0 + TBK, tid);
        }
        mma_tile(As[buf], Bs[buf], acc, wm, wn, lane);
        __syncthreads();
    }

    bf16* dst = (mat == 0) ? g_qT : g_kT;
    const float *gb = (mat == 0) ? gq : gk, *bb = (mat == 0) ? bq : bk;
    const float *mb = (mat == 0) ? mq : mk, *vb2 = (mat == 0) ? vq : vk;
    const float *eb = (mat == 0) ? betaq : betak;

    float sc[4][2], of[4][2];
    #pragma unroll
    for (int nt = 0; nt < 4; nt++) {
        #pragma unroll
        for (int h = 0; h < 2; h++) {
            int ch = c0 + wn * 32 + nt * 8 + 2 * tg + h;
            float inv = gb[ch] * rsqrtf(vb2[ch] + EPS_);
            sc[nt][h] = inv;
            of[nt][h] = (bb[ch] - mb[ch]) * inv + eb[ch];
        }
    }

    #pragma unroll
    for (int mt = 0; mt < 4; mt++) {
        int r0 = n0 + wm * 64 + mt * 16 + g;
        #pragma unroll
        for (int nt = 0; nt < 4; nt++) {
            int col = c0 + wn * 32 + nt * 8 + 2 * tg;
            float v00 = fmaxf(acc[mt][nt][0] * sc[nt][0] + of[nt][0], 0.0f);
            float v01 = fmaxf(acc[mt][nt][1] * sc[nt][1] + of[nt][1], 0.0f);
            float v10 = fmaxf(acc[mt][nt][2] * sc[nt][0] + of[nt][0], 0.0f);
            float v11 = fmaxf(acc[mt][nt][3] * sc[nt][1] + of[nt][1], 0.0f);
            *reinterpret_cast<unsigned*>(&dst[((size_t)b * N_ + r0) * MID_ + col]) = pack2(v00, v01);
            *reinterpret_cast<unsigned*>(&dst[((size_t)b * N_ + r0 + 8) * MID_ + col]) = pack2(v10, v11);
        }
    }
}

// ---------------------------------------------------------------------------
// projV: v projection. grid (N/128, MID/128, B), 256 thr.
// ---------------------------------------------------------------------------
__global__ __launch_bounds__(256, 2) void projV_mma(
    const float* __restrict__ x,
    const float* __restrict__ wv, const float* __restrict__ bv)
{
    __shared__ __align__(16) bf16 As[2][TBM * TSTR];
    __shared__ __align__(16) bf16 Bs[2][TBM * TSTR];

    const int b  = blockIdx.z;
    const int m0 = blockIdx.y * TBM;
    const int n0 = blockIdx.x * TBN;
    const int tid  = threadIdx.x;
    const int lane = tid & 31, wid = tid >> 5;
    const int wm = wid & 1, wn = wid >> 1;
    const int g = lane >> 2, tg = lane & 3;

    const float* xb = x + (size_t)b * C_ * N_;

    float acc[4][4][4] = {};

    stage_f32(As[0], wv + (size_t)m0 * C_, C_, 0, tid);
    stage_xT(Bs[0], xb, 0, n0, tid);
    __syncthreads();

    for (int k0 = 0; k0 < C_; k0 += TBK) {
        const int buf = (k0 / TBK) & 1;
        if (k0 + TBK < C_) {
            stage_f32(As[buf ^ 1], wv + (size_t)m0 * C_, C_, k0 + TBK, tid);
            stage_xT(Bs[buf ^ 1], xb, k0 + TBK, n0, tid);
        }
        mma_tile(As[buf], Bs[buf], acc, wm, wn, lane);
        __syncthreads();
    }

    #pragma unroll
    for (int mt = 0; mt < 4; mt++) {
        int r0 = m0 + wm * 64 + mt * 16 + g;
        int r1 = r0 + 8;
        float b0v = bv[r0], b1v = bv[r1];
        #pragma unroll
        for (int nt = 0; nt < 4; nt++) {
            int col = n0 + wn * 32 + nt * 8 + 2 * tg;
            *reinterpret_cast<unsigned*>(&g_v[((size_t)b * MID_ + r0) * N_ + col]) =
                pack2(acc[mt][nt][0] + b0v, acc[mt][nt][1] + b0v);
            *reinterpret_cast<unsigned*>(&g_v[((size_t)b * MID_ + r1) * N_ + col]) =
                pack2(acc[mt][nt][2] + b1v, acc[mt][nt][3] + b1v);
        }
    }
}

// ---------------------------------------------------------------------------
// attn_flash: fused scores + softmax(axis=i) + ctx.
//   ctx^T[j][c] = sum_i softmax_i(S^T[j][i]) v[c][i], S^T = (kT_j · qT_i)/16
// grid (N/JT=32, B), 256 thr (8 warps: jw 0..3 × cw 0..1).
// ---------------------------------------------------------------------------
struct __align__(16) AttnSmem {
    bf16 Ak[2][JT * TSTR];      // kT chunk [64j][40]
    bf16 Bq[2][IT * TSTR];      // qT chunk [64i][40]
    bf16 P[JT * VSTR];          // P tile [64j][72]
    bf16 V[MID_ * VSTR];        // v tile [256c][72]
    float M[JT], Ssum[JT];
    float pm[JT][2], ps[JT][2];
};

__device__ __forceinline__ void stage_chunk(bf16* T, const bf16* src, int k0, int tid)
{
    int row = tid >> 2, k8 = (tid & 3) * 8;
    *reinterpret_cast<uint4*>(&T[row * TSTR + k8]) =
        *reinterpret_cast<const uint4*>(&src[(size_t)row * MID_ + k0 + k8]);
}

__global__ __launch_bounds__(256, 2) void attn_flash()
{
    extern __shared__ char smem_raw[];
    AttnSmem* sm = reinterpret_cast<AttnSmem*>(smem_raw);

    const int b  = blockIdx.y;
    const int j0 = blockIdx.x * JT;
    const int tid  = threadIdx.x;
    const int lane = tid & 31, wid = tid >> 5;
    const int jw = wid & 3, cw = wid >> 2;
    const int g = lane >> 2, tg = lane & 3;
    const int arow = (lane & 15);
    const int akof = (lane >> 4) << 3;
    const int bcol = (lane & 7) + ((lane >> 4) << 3);
    const int bkof = (lane & 8);
    const int r0 = jw * 16 + g, r1 = r0 + 8;

    if (tid < JT) { sm->M[tid] = -3.0e38f; sm->Ssum[tid] = 0.0f; }

    const bf16* kTb = g_kT + ((size_t)b * N_ + j0) * MID_;
    const bf16* vb  = g_v + (size_t)b * MID_ * N_;

    float acc[16][4] = {};   // ctx accumulator: warp m16 x n128 (cw half)

    for (int it = 0; it < N_ / IT; it++) {
        const int i0 = it * IT;
        __syncthreads();   // prior phase C done (V/P safe to overwrite); stats init visible

        // stage V tile [256c][IT]: one row per thread
        {
            const bf16* vr = vb + (size_t)tid * N_ + i0;
            #pragma unroll
            for (int u = 0; u < 8; u++)
                *reinterpret_cast<uint4*>(&sm->V[tid * VSTR + u * 8]) =
                    *reinterpret_cast<const uint4*>(&vr[u * 8]);
        }

        // ---- Phase A: S tile [64j][64i], k = MID staged in 32-chunks ----
        const bf16* qTb = g_qT + ((size_t)b * N_ + i0) * MID_;
        stage_chunk(sm->Ak[0], kTb, 0, tid);
        stage_chunk(sm->Bq[0], qTb, 0, tid);
        __syncthreads();

        float sacc[4][4] = {};
        #pragma unroll
        for (int kc = 0; kc < MID_ / KC; kc++) {
            const int buf = kc & 1;
            if (kc + 1 < MID_ / KC) {
                stage_chunk(sm->Ak[buf ^ 1], kTb, (kc + 1) * KC, tid);
                stage_chunk(sm->Bq[buf ^ 1], qTb, (kc + 1) * KC, tid);
            }
            #pragma unroll
            for (int ks = 0; ks < 2; ks++) {
                const int kb = ks * 16;
                unsigned af[4];
                ldsm_x4(af, &sm->Ak[buf][(jw * 16 + arow) * TSTR + kb + akof]);
                unsigned bfr[4][2];
                #pragma unroll
                for (int np = 0; np < 2; np++) {
                    unsigned r4[4];
                    ldsm_x4(r4, &sm->Bq[buf][(cw * 32 + np * 16 + bcol) * TSTR + kb + bkof]);
                    bfr[np * 2][0]     = r4[0];
                    bfr[np * 2][1]     = r4[1];
                    bfr[np * 2 + 1][0] = r4[2];
                    bfr[np * 2 + 1][1] = r4[3];
                }
                #pragma unroll
                for (int nt = 0; nt < 4; nt++)
                    mma_bf16(sacc[nt], af, bfr[nt]);
            }
            __syncthreads();
        }

        // ---- Phase B: online softmax update ----
        // scale by 1/16 in place; per-lane row maxima for rows r0 (g) and r1 (g+8)
        float mg0 = -3.0e38f, mg1 = -3.0e38f;
        #pragma unroll
        for (int nt = 0; nt < 4; nt++) {
            sacc[nt][0] *= 0.0625f; sacc[nt][1] *= 0.0625f;
            sacc[nt][2] *= 0.0625f; sacc[nt][3] *= 0.0625f;
            mg0 = fmaxf(mg0, fmaxf(sacc[nt][0], sacc[nt][1]));
            mg1 = fmaxf(mg1, fmaxf(sacc[nt][2], sacc[nt][3]));
        }
        mg0 = fmaxf(mg0, __shfl_xor_sync(0xffffffffu, mg0, 1));
        mg0 = fmaxf(mg0, __shfl_xor_sync(0xffffffffu, mg0, 2));
        mg1 = fmaxf(mg1, __shfl_xor_sync(0xffffffffu, mg1, 1));
        mg1 = fmaxf(mg1, __shfl_xor_sync(0xffffffffu, mg1, 2));
        if (tg == 0) { sm->pm[r0][cw] = mg0; sm->pm[r1][cw] = mg1; }
        __syncthreads();   // sync1: pm visible

        float TM0 = fmaxf(sm->pm[r0][0], sm->pm[r0][1]);
        float TM1 = fmaxf(sm->pm[r1][0], sm->pm[r1][1]);
        float Mo0 = sm->M[r0], Mo1 = sm->M[r1];
        float Mn0 = fmaxf(Mo0, TM0), Mn1 = fmaxf(Mo1, TM1);
        float sc0 = __expf(Mo0 - Mn0), sc1 = __expf(Mo1 - Mn1);

        float rs0 = 0.0f, rs1 = 0.0f;
        #pragma unroll
        for (int nt = 0; nt < 4; nt++) {
            float p00 = __expf(sacc[nt][0] - Mn0);
            float p01 = __expf(sacc[nt][1] - Mn0);
            float p10 = __expf(sacc[nt][2] - Mn1);
            float p11 = __expf(sacc[nt][3] - Mn1);
            rs0 += p00 + p01;
            rs1 += p10 + p11;
            int col = cw * 32 + nt * 8 + 2 * tg;
            *reinterpret_cast<unsigned*>(&sm->P[r0 * VSTR + col]) = pack2(p00, p01);
            *reinterpret_cast<unsigned*>(&sm->P[r1 * VSTR + col]) = pack2(p10, p11);
        }
        rs0 += __shfl_xor_sync(0xffffffffu, rs0, 1);
        rs0 += __shfl_xor_sync(0xffffffffu, rs0, 2);
        rs1 += __shfl_xor_sync(0xffffffffu, rs1, 1);
        rs1 += __shfl_xor_sync(0xffffffffu, rs1, 2);
        if (tg == 0) { sm->ps[r0][cw] = rs0; sm->ps[r1][cw] = rs1; }

        // rescale ctx accumulator
        #pragma unroll
        for (int nt = 0; nt < 16; nt++) {
            acc[nt][0] *= sc0; acc[nt][1] *= sc0;
            acc[nt][2] *= sc1; acc[nt][3] *= sc1;
        }
        __syncthreads();   // sync2: P + ps visible; all reads of old M done

        if (cw == 0 && tg == 0) {
            sm->M[r0] = Mn0;
            sm->M[r1] = Mn1;
            sm->Ssum[r0] = sm->Ssum[r0] * sc0 + sm->ps[r0][0] + sm->ps[r0][1];
            sm->Ssum[r1] = sm->Ssum[r1] * sc1 + sm->ps[r1][0] + sm->ps[r1][1];
        }

        // ---- Phase C: ctx accumulate: m16(j) x n128(c half) x k64(i) ----
        #pragma unroll
        for (int ks = 0; ks < 4; ks++) {
            const int kb = ks * 16;
            unsigned af[4];
            ldsm_x4(af, &sm->P[(jw * 16 + arow) * VSTR + kb + akof]);
            #pragma unroll
            for (int np = 0; np < 8; np++) {
                unsigned r4[4];
                ldsm_x4(r4, &sm->V[(cw * 128 + np * 16 + bcol) * VSTR + kb + bkof]);
                unsigned b0[2] = {r4[0], r4[1]};
                unsigned b1[2] = {r4[2], r4[3]};
                mma_bf16(acc[np * 2], af, b0);
                mma_bf16(acc[np * 2 + 1], af, b1);
            }
        }
    }

    // ---- Epilogue: normalize and write ctx^T ----
    __syncthreads();
    float inv0 = 1.0f / sm->Ssum[r0];
    float inv1 = 1.0f / sm->Ssum[r1];
    #pragma unroll
    for (int nt = 0; nt < 16; nt++) {
        int col = cw * 128 + nt * 8 + 2 * tg;
        *reinterpret_cast<unsigned*>(&g_ctxT[((size_t)b * N_ + j0 + r0) * MID_ + col]) =
            pack2(acc[nt][0] * inv0, acc[nt][1] * inv0);
        *reinterpret_cast<unsigned*>(&g_ctxT[((size_t)b * N_ + j0 + r1) * MID_ + col]) =
            pack2(acc[nt][2] * inv1, acc[nt][3] * inv1);
    }
}

// ---------------------------------------------------------------------------
// out: out[c'][n] = x + sum_m wo[c'][m] ctx^T[n][m] + bo[c']
// grid (N/128, C/128, B), 256 thr.
// ---------------------------------------------------------------------------
__global__ __launch_bounds__(256, 2) void out_mma(
    const float* __restrict__ x,
    const float* __restrict__ wo,
    const float* __restrict__ bo,
    float* __restrict__ out)
{
    __shared__ __align__(16) bf16 As[2][TBM * TSTR];
    __shared__ __align__(16) bf16 Bs[2][TBM * TSTR];

    const int b  = blockIdx.z;
    const int m0 = blockIdx.y * TBM;
    const int n0 = blockIdx.x * TBN;
    const int tid  = threadIdx.x;
    const int lane = tid & 31, wid = tid >> 5;
    const int wm = wid & 1, wn = wid >> 1;
    const int g = lane >> 2, tg = lane & 3;

    const bf16* cT = g_ctxT + ((size_t)b * N_ + n0) * MID_;

    float acc[4][4][4] = {};

    stage_f32(As[0], wo + (size_t)m0 * MID_, MID_, 0, tid);
    stage_bf16(Bs[0], cT, MID_, 0, tid);
    __syncthreads();

    for (int k0 = 0; k0 < MID_; k0 += TBK) {
        const int buf = (k0 / TBK) & 1;
        if (k0 + TBK < MID_) {
            stage_f32(As[buf ^ 1], wo + (size_t)m0 * MID_, MID_, k0 + TBK, tid);
            stage_bf16(Bs[buf ^ 1], cT, MID_, k0 + TBK, tid);
        }
        mma_tile(As[buf], Bs[buf], acc, wm, wn, lane);
        __syncthreads();
    }

    #pragma unroll
    for (int mt = 0; mt < 4; mt++) {
        int r0 = m0 + wm * 64 + mt * 16 + g;
        int r1 = r0 + 8;
        float bo0 = bo[r0], bo1 = bo[r1];
        #pragma unroll
        for (int nt = 0; nt < 4; nt++) {
            int col = n0 + wn * 32 + nt * 8 + 2 * tg;
            size_t a0 = ((size_t)b * C_ + r0) * N_ + col;
            size_t a1 = ((size_t)b * C_ + r1) * N_ + col;
            float2 x0 = *reinterpret_cast<const float2*>(&x[a0]);
            float2 x1 = *reinterpret_cast<const float2*>(&x[a1]);
            float2 v0 = {acc[mt][nt][0] + bo0 + x0.x, acc[mt][nt][1] + bo0 + x0.y};
            float2 v1 = {acc[mt][nt][2] + bo1 + x1.x, acc[mt][nt][3] + bo1 + x1.y};
            *reinterpret_cast<float2*>(&out[a0]) = v0;
            *reinterpret_cast<float2*>(&out[a1]) = v1;
        }
    }
}

// ---------------------------------------------------------------------------
extern "C" void kernel_launch(void* const* d_in, const int* in_sizes, int n_in,
                              void* d_out, int out_size)
{
    (void)in_sizes; (void)n_in; (void)out_size;
    const float* x     = (const float*)d_in[0];
    const float* wq    = (const float*)d_in[1];
    const float* bq    = (const float*)d_in[2];
    const float* gq    = (const float*)d_in[3];
    const float* betaq = (const float*)d_in[4];
    const float* wk    = (const float*)d_in[5];
    const float* bk    = (const float*)d_in[6];
    const float* gk    = (const float*)d_in[7];
    const float* betak = (const float*)d_in[8];
    const float* wv    = (const float*)d_in[9];
    const float* bv    = (const float*)d_in[10];
    const float* wo    = (const float*)d_in[11];
    const float* bo    = (const float*)d_in[12];
    const float* mq    = (const float*)d_in[13];
    const float* vq    = (const float*)d_in[14];
    const float* mk    = (const float*)d_in[15];
    const float* vk    = (const float*)d_in[16];
    float* out = (float*)d_out;

    static_assert(sizeof(AttnSmem) < 100 * 1024, "smem");
    cudaFuncSetAttribute(attn_flash, cudaFuncAttributeMaxDynamicSharedMemorySize,
                         (int)sizeof(AttnSmem));

    dim3 blk(256);
    projT_mma<<<dim3(MID_/TBN, N_/TBM, 2*B_), blk>>>(
        x, wq, bq, gq, betaq, mq, vq, wk, bk, gk, betak, mk, vk);
    projV_mma<<<dim3(N_/TBN, MID_/TBM, B_), blk>>>(x, wv, bv);
    attn_flash<<<dim3(N_/JT, B_), blk, sizeof(AttnSmem)>>>();
    out_mma<<<dim3(N_/TBN, C_/TBM, B_), blk>>>(x, wo, bo, out);
}

// round 12
// speedup vs baseline: 1.3712x; 1.3712x over previous
#include <cuda_runtime.h>
#include <cuda_bf16.h>
#include <math.h>

// Problem constants
constexpr int B_   = 16;
constexpr int C_   = 512;
constexpr int MID_ = 256;
constexpr int N_   = 2048;
constexpr float EPS_ = 1e-5f;

// MMA tiling
constexpr int TBM = 128;
constexpr int TBN = 128;
constexpr int TBK = 32;
constexpr int TSTR = 40;   // bf16 row stride (80B), ldmatrix conflict-free
constexpr int NIB = 16;    // number of i-blocks (N/TBN) for softmax partials

// ctx kernel: wider k chunks
constexpr int CBK  = 64;
constexpr int CSTR = 72;   // 144B rows, 16B aligned, ldsm conflict-free

typedef __nv_bfloat16 bf16;
typedef __nv_bfloat162 bf162;

// Scratch
__device__ bf16 g_qT[(size_t)B_ * N_ * MID_];   // q^T: [b][n][mid]
__device__ bf16 g_kT[(size_t)B_ * N_ * MID_];   // k^T: [b][n][mid]
__device__ bf16 g_v [(size_t)B_ * MID_ * N_];   // v:   [b][mid][n]
__device__ bf16 g_sT[(size_t)B_ * N_ * N_];     // S^T: [b][j][i]
__device__ bf16 g_ctxT[(size_t)B_ * N_ * MID_]; // ctx^T: [b][n][mid]
__device__ float g_pmax[(size_t)B_ * NIB * N_];
__device__ float g_psum[(size_t)B_ * NIB * N_];
__device__ float g_cmax[B_ * N_];
__device__ float g_cinv[B_ * N_];

__device__ __forceinline__ unsigned pack2(float lo, float hi) {
    bf162 h = __floats2bfloat162_rn(lo, hi);
    return *reinterpret_cast<unsigned*>(&h);
}

__device__ __forceinline__ void mma_bf16(float c[4], const unsigned a[4], const unsigned b[2])
{
    asm volatile(
        "mma.sync.aligned.m16n8k16.row.col.f32.bf16.bf16.f32 "
        "{%0,%1,%2,%3}, {%4,%5,%6,%7}, {%8,%9}, {%0,%1,%2,%3};\n"
        : "+f"(c[0]), "+f"(c[1]), "+f"(c[2]), "+f"(c[3])
        : "r"(a[0]), "r"(a[1]), "r"(a[2]), "r"(a[3]),
          "r"(b[0]), "r"(b[1]));
}

__device__ __forceinline__ void ldsm_x4(unsigned r[4], const bf16* p)
{
    unsigned addr = (unsigned)__cvta_generic_to_shared(p);
    asm volatile(
        "ldmatrix.sync.aligned.m8n8.x4.shared.b16 {%0,%1,%2,%3}, [%4];\n"
        : "=r"(r[0]), "=r"(r[1]), "=r"(r[2]), "=r"(r[3]) : "r"(addr));
}

// k-loop step over one k-tile with KSTEPS x16, row stride STR.
template<int STR, int KSTEPS>
__device__ __forceinline__ void mma_tile_t(const bf16* TA, const bf16* TB,
                                           float acc[4][4][4],
                                           int wm, int wn, int lane)
{
    const int arow = (lane & 15);
    const int akof = (lane >> 4) << 3;
    const int bcol = (lane & 7) + ((lane >> 4) << 3);
    const int bkof = (lane & 8);

    #pragma unroll
    for (int ks = 0; ks < KSTEPS; ks++) {
        const int kb = ks * 16;
        unsigned af[4][4], bfr[4][2];
        #pragma unroll
        for (int mt = 0; mt < 4; mt++) {
            int row = wm * 64 + mt * 16 + arow;
            ldsm_x4(af[mt], &TA[row * STR + kb + akof]);
        }
        #pragma unroll
        for (int np = 0; np < 2; np++) {
            unsigned r4[4];
            int col = wn * 32 + np * 16 + bcol;
            ldsm_x4(r4, &TB[col * STR + kb + bkof]);
            bfr[np * 2][0]     = r4[0];
            bfr[np * 2][1]     = r4[1];
            bfr[np * 2 + 1][0] = r4[2];
            bfr[np * 2 + 1][1] = r4[3];
        }
        #pragma unroll
        for (int mt = 0; mt < 4; mt++)
            #pragma unroll
            for (int nt = 0; nt < 4; nt++)
                mma_bf16(acc[mt][nt], af[mt], bfr[nt]);
    }
}

__device__ __forceinline__ void stage_bf16(bf16* T, const bf16* src, size_t gstride,
                                           int k0, int tid)
{
    #pragma unroll
    for (int r = 0; r < 2; r++) {
        int f = tid + r * 256;
        int row = f >> 2, k8 = (f & 3) * 8;
        *reinterpret_cast<uint4*>(&T[row * TSTR + k8]) =
            *reinterpret_cast<const uint4*>(&src[(size_t)row * gstride + k0 + k8]);
    }
}

__device__ __forceinline__ void stage_f32(bf16* T, const float* src, size_t gstride,
                                          int k0, int tid)
{
    #pragma unroll
    for (int r = 0; r < 4; r++) {
        int f = tid + r * 256;
        int row = f >> 3, k4 = (f & 7) * 4;
        float4 w4 = *reinterpret_cast<const float4*>(&src[(size_t)row * gstride + k0 + k4]);
        uint2 p;
        p.x = pack2(w4.x, w4.y);
        p.y = pack2(w4.z, w4.w);
        *reinterpret_cast<uint2*>(&T[row * TSTR + k4]) = p;
    }
}

__device__ __forceinline__ void stage_xT(bf16* T, const float* xb, int k0, int n0, int tid)
{
    #pragma unroll
    for (int r = 0; r < 16; r++) {
        int f = tid + r * 256;
        int c = f >> 7, n = f & 127;
        T[n * TSTR + c] = __float2bfloat16(xb[(size_t)(k0 + c) * N_ + n0 + n]);
    }
}

// ---------------------------------------------------------------------------
// projT: q/k projection, transposed output. grid (MID/128, N/128, 2B), 256 thr.
// ---------------------------------------------------------------------------
__global__ __launch_bounds__(256, 2) void projT_mma(
    const float* __restrict__ x,
    const float* __restrict__ wq, const float* __restrict__ bq,
    const float* __restrict__ gq, const float* __restrict__ betaq,
    const float* __restrict__ mq, const float* __restrict__ vq,
    const float* __restrict__ wk, const float* __restrict__ bk,
    const float* __restrict__ gk, const float* __restrict__ betak,
    const float* __restrict__ mk, const float* __restrict__ vk)
{
    __shared__ __align__(16) bf16 As[2][TBM * TSTR];
    __shared__ __align__(16) bf16 Bs[2][TBM * TSTR];

    const int mat = blockIdx.z / B_;
    const int b   = blockIdx.z % B_;
    const int n0  = blockIdx.y * TBM;
    const int c0  = blockIdx.x * TBN;
    const int tid  = threadIdx.x;
    const int lane = tid & 31, wid = tid >> 5;
    const int wm = wid & 1, wn = wid >> 1;
    const int g = lane >> 2, tg = lane & 3;

    const float* w  = (mat == 0) ? wq : wk;
    const float* xb = x + (size_t)b * C_ * N_;

    float acc[4][4][4] = {};

    stage_xT(As[0], xb, 0, n0, tid);
    stage_f32(Bs[0], w + (size_t)c0 * C_, C_, 0, tid);
    __syncthreads();

    for (int k0 = 0; k0 < C_; k0 += TBK) {
        const int buf = (k0 / TBK) & 1;
        if (k0 + TBK < C_) {
            stage_xT(As[buf ^ 1], xb, k0 + TBK, n0, tid);
            stage_f32(Bs[buf ^ 1], w + (size_t)c0 * C_, C_, k0 + TBK, tid);
        }
        mma_tile_t<TSTR, 2>(As[buf], Bs[buf], acc, wm, wn, lane);
        __syncthreads();
    }

    bf16* dst = (mat == 0) ? g_qT : g_kT;
    const float *gb = (mat == 0) ? gq : gk, *bb = (mat == 0) ? bq : bk;
    const float *mb = (mat == 0) ? mq : mk, *vb2 = (mat == 0) ? vq : vk;
    const float *eb = (mat == 0) ? betaq : betak;

    float sc[4][2], of[4][2];
    #pragma unroll
    for (int nt = 0; nt < 4; nt++) {
        #pragma unroll
        for (int h = 0; h < 2; h++) {
            int ch = c0 + wn * 32 + nt * 8 + 2 * tg + h;
            float inv = gb[ch] * rsqrtf(vb2[ch] + EPS_);
            sc[nt][h] = inv;
            of[nt][h] = (bb[ch] - mb[ch]) * inv + eb[ch];
        }
    }

    #pragma unroll
    for (int mt = 0; mt < 4; mt++) {
        int r0 = n0 + wm * 64 + mt * 16 + g;
        #pragma unroll
        for (int nt = 0; nt < 4; nt++) {
            int col = c0 + wn * 32 + nt * 8 + 2 * tg;
            float v00 = fmaxf(acc[mt][nt][0] * sc[nt][0] + of[nt][0], 0.0f);
            float v01 = fmaxf(acc[mt][nt][1] * sc[nt][1] + of[nt][1], 0.0f);
            float v10 = fmaxf(acc[mt][nt][2] * sc[nt][0] + of[nt][0], 0.0f);
            float v11 = fmaxf(acc[mt][nt][3] * sc[nt][1] + of[nt][1], 0.0f);
            *reinterpret_cast<unsigned*>(&dst[((size_t)b * N_ + r0) * MID_ + col]) = pack2(v00, v01);
            *reinterpret_cast<unsigned*>(&dst[((size_t)b * N_ + r0 + 8) * MID_ + col]) = pack2(v10, v11);
        }
    }
}

// ---------------------------------------------------------------------------
// projV: v projection. grid (N/128, MID/128, B), 256 thr.
// ---------------------------------------------------------------------------
__global__ __launch_bounds__(256, 2) void projV_mma(
    const float* __restrict__ x,
    const float* __restrict__ wv, const float* __restrict__ bv)
{
    __shared__ __align__(16) bf16 As[2][TBM * TSTR];
    __shared__ __align__(16) bf16 Bs[2][TBM * TSTR];

    const int b  = blockIdx.z;
    const int m0 = blockIdx.y * TBM;
    const int n0 = blockIdx.x * TBN;
    const int tid  = threadIdx.x;
    const int lane = tid & 31, wid = tid >> 5;
    const int wm = wid & 1, wn = wid >> 1;
    const int g = lane >> 2, tg = lane & 3;

    const float* xb = x + (size_t)b * C_ * N_;

    float acc[4][4][4] = {};

    stage_f32(As[0], wv + (size_t)m0 * C_, C_, 0, tid);
    stage_xT(Bs[0], xb, 0, n0, tid);
    __syncthreads();

    for (int k0 = 0; k0 < C_; k0 += TBK) {
        const int buf = (k0 / TBK) & 1;
        if (k0 + TBK < C_) {
            stage_f32(As[buf ^ 1], wv + (size_t)m0 * C_, C_, k0 + TBK, tid);
            stage_xT(Bs[buf ^ 1], xb, k0 + TBK, n0, tid);
        }
        mma_tile_t<TSTR, 2>(As[buf], Bs[buf], acc, wm, wn, lane);
        __syncthreads();
    }

    #pragma unroll
    for (int mt = 0; mt < 4; mt++) {
        int r0 = m0 + wm * 64 + mt * 16 + g;
        int r1 = r0 + 8;
        float b0v = bv[r0], b1v = bv[r1];
        #pragma unroll
        for (int nt = 0; nt < 4; nt++) {
            int col = n0 + wn * 32 + nt * 8 + 2 * tg;
            *reinterpret_cast<unsigned*>(&g_v[((size_t)b * MID_ + r0) * N_ + col]) =
                pack2(acc[mt][nt][0] + b0v, acc[mt][nt][1] + b0v);
            *reinterpret_cast<unsigned*>(&g_v[((size_t)b * MID_ + r1) * N_ + col]) =
                pack2(acc[mt][nt][2] + b1v, acc[mt][nt][3] + b1v);
        }
    }
}

// ---------------------------------------------------------------------------
// scores: S^T[j][i] = (1/16) sum_m k[m][j] q[m][i]; epilogue also emits
// per-(j, i-block) partial softmax stats (max, sumexp) from fp32 accumulators.
// grid (N/128 i, N/128 j, B), 256 thr.
// ---------------------------------------------------------------------------
__global__ __launch_bounds__(256, 2) void scores_mma()
{
    __shared__ __align__(16) bf16 As[2][TBM * TSTR];
    __shared__ __align__(16) bf16 Bs[2][TBM * TSTR];
    __shared__ float pmS[TBM][4], psS[TBM][4];

    const int b    = blockIdx.z;
    const int j0   = blockIdx.y * TBM;
    const int i0   = blockIdx.x * TBN;
    const int iblk = blockIdx.x;
    const int tid  = threadIdx.x;
    const int lane = tid & 31, wid = tid >> 5;
    const int wm = wid & 1, wn = wid >> 1;
    const int g = lane >> 2, tg = lane & 3;

    const bf16* kT = g_kT + ((size_t)b * N_ + j0) * MID_;
    const bf16* qT = g_qT + ((size_t)b * N_ + i0) * MID_;

    float acc[4][4][4] = {};

    stage_bf16(As[0], kT, MID_, 0, tid);
    stage_bf16(Bs[0], qT, MID_, 0, tid);
    __syncthreads();

    for (int k0 = 0; k0 < MID_; k0 += TBK) {
        const int buf = (k0 / TBK) & 1;
        if (k0 + TBK < MID_) {
            stage_bf16(As[buf ^ 1], kT, MID_, k0 + TBK, tid);
            stage_bf16(Bs[buf ^ 1], qT, MID_, k0 + TBK, tid);
        }
        mma_tile_t<TSTR, 2>(As[buf], Bs[buf], acc, wm, wn, lane);
        __syncthreads();
    }

    // scale in place, store S^T
    #pragma unroll
    for (int mt = 0; mt < 4; mt++) {
        #pragma unroll
        for (int nt = 0; nt < 4; nt++) {
            acc[mt][nt][0] *= 0.0625f; acc[mt][nt][1] *= 0.0625f;
            acc[mt][nt][2] *= 0.0625f; acc[mt][nt][3] *= 0.0625f;
            int row = j0 + wm * 64 + mt * 16 + g;
            int col = i0 + wn * 32 + nt * 8 + 2 * tg;
            *reinterpret_cast<unsigned*>(&g_sT[((size_t)b * N_ + row) * N_ + col]) =
                pack2(acc[mt][nt][0], acc[mt][nt][1]);
            *reinterpret_cast<unsigned*>(&g_sT[((size_t)b * N_ + row + 8) * N_ + col]) =
                pack2(acc[mt][nt][2], acc[mt][nt][3]);
        }
    }

    // ---- partial softmax stats over this CTA's 128 i-cols ----
    // per-warp row maxima (32 cols) -> pmS[row][wn]
    #pragma unroll
    for (int mt = 0; mt < 4; mt++) {
        float m0 = -3.0e38f, m1 = -3.0e38f;
        #pragma unroll
        for (int nt = 0; nt < 4; nt++) {
            m0 = fmaxf(m0, fmaxf(acc[mt][nt][0], acc[mt][nt][1]));
            m1 = fmaxf(m1, fmaxf(acc[mt][nt][2], acc[mt][nt][3]));
        }
        m0 = fmaxf(m0, __shfl_xor_sync(0xffffffffu, m0, 1));
        m0 = fmaxf(m0, __shfl_xor_sync(0xffffffffu, m0, 2));
        m1 = fmaxf(m1, __shfl_xor_sync(0xffffffffu, m1, 1));
        m1 = fmaxf(m1, __shfl_xor_sync(0xffffffffu, m1, 2));
        if (tg == 0) {
            pmS[wm * 64 + mt * 16 + g][wn] = m0;
            pmS[wm * 64 + mt * 16 + g + 8][wn] = m1;
        }
    }
    __syncthreads();

    // per-warp sumexp with block-row max -> psS[row][wn]
    #pragma unroll
    for (int mt = 0; mt < 4; mt++) {
        int row0 = wm * 64 + mt * 16 + g, row1 = row0 + 8;
        float TM0 = fmaxf(fmaxf(pmS[row0][0], pmS[row0][1]), fmaxf(pmS[row0][2], pmS[row0][3]));
        float TM1 = fmaxf(fmaxf(pmS[row1][0], pmS[row1][1]), fmaxf(pmS[row1][2], pmS[row1][3]));
        float s0 = 0.0f, s1 = 0.0f;
        #pragma unroll
        for (int nt = 0; nt < 4; nt++) {
            s0 += __expf(acc[mt][nt][0] - TM0) + __expf(acc[mt][nt][1] - TM0);
            s1 += __expf(acc[mt][nt][2] - TM1) + __expf(acc[mt][nt][3] - TM1);
        }
        s0 += __shfl_xor_sync(0xffffffffu, s0, 1);
        s0 += __shfl_xor_sync(0xffffffffu, s0, 2);
        s1 += __shfl_xor_sync(0xffffffffu, s1, 1);
        s1 += __shfl_xor_sync(0xffffffffu, s1, 2);
        if (tg == 0) { psS[row0][wn] = s0; psS[row1][wn] = s1; }
    }
    __syncthreads();

    // warps wn==0 (wid 0,1) write the per-block partials
    if (wn == 0 && tg == 0) {
        #pragma unroll
        for (int mt = 0; mt < 4; mt++) {
            #pragma unroll
            for (int h = 0; h < 2; h++) {
                int row = wm * 64 + mt * 16 + g + h * 8;
                float TM = fmaxf(fmaxf(pmS[row][0], pmS[row][1]), fmaxf(pmS[row][2], pmS[row][3]));
                float S  = psS[row][0] + psS[row][1] + psS[row][2] + psS[row][3];
                size_t idx = ((size_t)b * NIB + iblk) * N_ + j0 + row;
                g_pmax[idx] = TM;
                g_psum[idx] = S;
            }
        }
    }
}

// ---------------------------------------------------------------------------
// colcomb: combine NIB partials per (b, j). grid (N/256, B), 256 thr.
// ---------------------------------------------------------------------------
__global__ __launch_bounds__(256) void colcomb_kernel()
{
    const int j = blockIdx.x * 256 + threadIdx.x;
    const int b = blockIdx.y;
    float M = -3.0e38f, S = 0.0f;
    #pragma unroll
    for (int p = 0; p < NIB; p++) {
        float m2 = g_pmax[((size_t)b * NIB + p) * N_ + j];
        float s2 = g_psum[((size_t)b * NIB + p) * N_ + j];
        float mn = fmaxf(M, m2);
        S = S * __expf(M - mn) + s2 * __expf(m2 - mn);
        M = mn;
    }
    g_cmax[b * N_ + j] = M;
    g_cinv[b * N_ + j] = 1.0f / S;
}

// ---------------------------------------------------------------------------
// ctx: ctx^T[j][c] = sum_i P[i][j] v[c][i], P = exp(S^T[j][i]-cm[j])*ci[j]
// k-chunks of 64, dynamic smem. grid (MID/128=2, N/128=16, B), 256 thr.
// ---------------------------------------------------------------------------
struct __align__(16) CtxSmem {
    bf16 As[2][TBM * CSTR];
    bf16 Bs[2][TBM * CSTR];
    float cm[TBM], ci[TBM];
};

__global__ __launch_bounds__(256, 2) void ctx_mma()
{
    extern __shared__ char smem_raw[];
    CtxSmem* sm = reinterpret_cast<CtxSmem*>(smem_raw);

    const int b  = blockIdx.z;
    const int j0 = blockIdx.y * TBM;
    const int c0 = blockIdx.x * TBN;
    const int tid  = threadIdx.x;
    const int lane = tid & 31, wid = tid >> 5;
    const int wm = wid & 1, wn = wid >> 1;
    const int g = lane >> 2, tg = lane & 3;

    if (tid < TBM) {
        sm->cm[tid] = g_cmax[b * N_ + j0 + tid];
        sm->ci[tid] = g_cinv[b * N_ + j0 + tid];
    }
    __syncthreads();

    const bf16* sT = g_sT + ((size_t)b * N_ + j0) * N_;
    const bf16* vb = g_v + ((size_t)b * MID_ + c0) * N_;

    float acc[4][4][4] = {};

    auto stage_P = [&](bf16* T, int k0) {
        #pragma unroll
        for (int r = 0; r < 4; r++) {
            int f = tid + r * 256;
            int row = f >> 3, i8 = (f & 7) * 8;
            uint4 raw4 = *reinterpret_cast<const uint4*>(&sT[(size_t)row * N_ + k0 + i8]);
            const unsigned u[4] = {raw4.x, raw4.y, raw4.z, raw4.w};
            float cmv = sm->cm[row], civ = sm->ci[row];
            unsigned po[4];
            #pragma unroll
            for (int q = 0; q < 4; q++) {
                float2 fv = __bfloat1622float2(*reinterpret_cast<const bf162*>(&u[q]));
                po[q] = pack2(__expf(fv.x - cmv) * civ, __expf(fv.y - cmv) * civ);
            }
            uint4 o = {po[0], po[1], po[2], po[3]};
            *reinterpret_cast<uint4*>(&T[row * CSTR + i8]) = o;
        }
    };
    auto stage_V = [&](bf16* T, int k0) {
        #pragma unroll
        for (int r = 0; r < 4; r++) {
            int f = tid + r * 256;
            int row = f >> 3, i8 = (f & 7) * 8;
            *reinterpret_cast<uint4*>(&T[row * CSTR + i8]) =
                *reinterpret_cast<const uint4*>(&vb[(size_t)row * N_ + k0 + i8]);
        }
    };

    stage_P(sm->As[0], 0);
    stage_V(sm->Bs[0], 0);
    __syncthreads();

    for (int k0 = 0; k0 < N_; k0 += CBK) {
        const int buf = (k0 / CBK) & 1;
        if (k0 + CBK < N_) {
            stage_P(sm->As[buf ^ 1], k0 + CBK);
            stage_V(sm->Bs[buf ^ 1], k0 + CBK);
        }
        mma_tile_t<CSTR, 4>(sm->As[buf], sm->Bs[buf], acc, wm, wn, lane);
        __syncthreads();
    }

    #pragma unroll
    for (int mt = 0; mt < 4; mt++) {
        int row = j0 + wm * 64 + mt * 16 + g;
        #pragma unroll
        for (int nt = 0; nt < 4; nt++) {
            int col = c0 + wn * 32 + nt * 8 + 2 * tg;
            *reinterpret_cast<unsigned*>(&g_ctxT[((size_t)b * N_ + row) * MID_ + col]) =
                pack2(acc[mt][nt][0], acc[mt][nt][1]);
            *reinterpret_cast<unsigned*>(&g_ctxT[((size_t)b * N_ + row + 8) * MID_ + col]) =
                pack2(acc[mt][nt][2], acc[mt][nt][3]);
        }
    }
}

// ---------------------------------------------------------------------------
// out: out[c'][n] = x + sum_m wo[c'][m] ctx^T[n][m] + bo[c']
// grid (N/128, C/128, B), 256 thr.
// ---------------------------------------------------------------------------
__global__ __launch_bounds__(256, 2) void out_mma(
    const float* __restrict__ x,
    const float* __restrict__ wo,
    const float* __restrict__ bo,
    float* __restrict__ out)
{
    __shared__ __align__(16) bf16 As[2][TBM * TSTR];
    __shared__ __align__(16) bf16 Bs[2][TBM * TSTR];

    const int b  = blockIdx.z;
    const int m0 = blockIdx.y * TBM;
    const int n0 = blockIdx.x * TBN;
    const int tid  = threadIdx.x;
    const int lane = tid & 31, wid = tid >> 5;
    const int wm = wid & 1, wn = wid >> 1;
    const int g = lane >> 2, tg = lane & 3;

    const bf16* cT = g_ctxT + ((size_t)b * N_ + n0) * MID_;

    float acc[4][4][4] = {};

    stage_f32(As[0], wo + (size_t)m0 * MID_, MID_, 0, tid);
    stage_bf16(Bs[0], cT, MID_, 0, tid);
    __syncthreads();

    for (int k0 = 0; k0 < MID_; k0 += TBK) {
        const int buf = (k0 / TBK) & 1;
        if (k0 + TBK < MID_) {
            stage_f32(As[buf ^ 1], wo + (size_t)m0 * MID_, MID_, k0 + TBK, tid);
            stage_bf16(Bs[buf ^ 1], cT, MID_, k0 + TBK, tid);
        }
        mma_tile_t<TSTR, 2>(As[buf], Bs[buf], acc, wm, wn, lane);
        __syncthreads();
    }

    #pragma unroll
    for (int mt = 0; mt < 4; mt++) {
        int r0 = m0 + wm * 64 + mt * 16 + g;
        int r1 = r0 + 8;
        float bo0 = bo[r0], bo1 = bo[r1];
        #pragma unroll
        for (int nt = 0; nt < 4; nt++) {
            int col = n0 + wn * 32 + nt * 8 + 2 * tg;
            size_t a0 = ((size_t)b * C_ + r0) * N_ + col;
            size_t a1 = ((size_t)b * C_ + r1) * N_ + col;
            float2 x0 = *reinterpret_cast<const float2*>(&x[a0]);
            float2 x1 = *reinterpret_cast<const float2*>(&x[a1]);
            float2 v0 = {acc[mt][nt][0] + bo0 + x0.x, acc[mt][nt][1] + bo0 + x0.y};
            float2 v1 = {acc[mt][nt][2] + bo1 + x1.x, acc[mt][nt][3] + bo1 + x1.y};
            *reinterpret_cast<float2*>(&out[a0]) = v0;
            *reinterpret_cast<float2*>(&out[a1]) = v1;
        }
    }
}

// ---------------------------------------------------------------------------
extern "C" void kernel_launch(void* const* d_in, const int* in_sizes, int n_in,
                              void* d_out, int out_size)
{
    (void)in_sizes; (void)n_in; (void)out_size;
    const float* x     = (const float*)d_in[0];
    const float* wq    = (const float*)d_in[1];
    const float* bq    = (const float*)d_in[2];
    const float* gq    = (const float*)d_in[3];
    const float* betaq = (const float*)d_in[4];
    const float* wk    = (const float*)d_in[5];
    const float* bk    = (const float*)d_in[6];
    const float* gk    = (const float*)d_in[7];
    const float* betak = (const float*)d_in[8];
    const float* wv    = (const float*)d_in[9];
    const float* bv    = (const float*)d_in[10];
    const float* wo    = (const float*)d_in[11];
    const float* bo    = (const float*)d_in[12];
    const float* mq    = (const float*)d_in[13];
    const float* vq    = (const float*)d_in[14];
    const float* mk    = (const float*)d_in[15];
    const float* vk    = (const float*)d_in[16];
    float* out = (float*)d_out;

    cudaFuncSetAttribute(ctx_mma, cudaFuncAttributeMaxDynamicSharedMemorySize,
                         (int)sizeof(CtxSmem));

    dim3 blk(256);
    projT_mma<<<dim3(MID_/TBN, N_/TBM, 2*B_), blk>>>(
        x, wq, bq, gq, betaq, mq, vq, wk, bk, gk, betak, mk, vk);
    projV_mma<<<dim3(N_/TBN, MID_/TBM, B_), blk>>>(x, wv, bv);
    scores_mma<<<dim3(N_/TBN, N_/TBM, B_), blk>>>();
    colcomb_kernel<<<dim3(N_/256, B_), blk>>>();
    ctx_mma<<<dim3(MID_/TBN, N_/TBM, B_), blk, sizeof(CtxSmem)>>>();
    out_mma<<<dim3(N_/TBN, C_/TBM, B_), blk>>>(x, wo, bo, out);
}

// round 15
// speedup vs baseline: 1.6355x; 1.1927x over previous
#include <cuda_runtime.h>
#include <cuda_bf16.h>
#include <math.h>

// Problem constants
constexpr int B_   = 16;
constexpr int C_   = 512;
constexpr int MID_ = 256;
constexpr int N_   = 2048;
constexpr float EPS_ = 1e-5f;

// MMA tiling
constexpr int TBM = 128;
constexpr int TBN = 128;
constexpr int TBK = 32;    // k-chunk for out kernel
constexpr int TSTR = 40;   // bf16 row stride (80B), ldmatrix conflict-free
constexpr int NIB = 16;    // i-blocks for softmax partials

// wide k-chunk kernels
constexpr int CBK  = 64;
constexpr int CSTR = 72;   // 144B rows, ldsm conflict-free
constexpr int PBK  = 64;   // proj k-chunk
constexpr int XSTR = 136;  // x tile [c][n] row stride (272B), trans-ldsm conflict-free

typedef __nv_bfloat16 bf16;
typedef __nv_bfloat162 bf162;

// Scratch
__device__ bf16 g_qT[(size_t)B_ * N_ * MID_];   // q^T: [b][n][mid]
__device__ bf16 g_kT[(size_t)B_ * N_ * MID_];   // k^T: [b][n][mid]
__device__ bf16 g_v [(size_t)B_ * MID_ * N_];   // v:   [b][mid][n]
__device__ bf16 g_sT[(size_t)B_ * N_ * N_];     // S^T: [b][j][i]
__device__ bf16 g_ctxT[(size_t)B_ * N_ * MID_]; // ctx^T: [b][n][mid]
__device__ float g_pmax[(size_t)B_ * NIB * N_];
__device__ float g_psum[(size_t)B_ * NIB * N_];
__device__ float g_cmax[B_ * N_];
__device__ float g_cinv[B_ * N_];

__device__ __forceinline__ unsigned pack2(float lo, float hi) {
    bf162 h = __floats2bfloat162_rn(lo, hi);
    return *reinterpret_cast<unsigned*>(&h);
}

__device__ __forceinline__ void mma_bf16(float c[4], const unsigned a[4], const unsigned b[2])
{
    asm volatile(
        "mma.sync.aligned.m16n8k16.row.col.f32.bf16.bf16.f32 "
        "{%0,%1,%2,%3}, {%4,%5,%6,%7}, {%8,%9}, {%0,%1,%2,%3};\n"
        : "+f"(c[0]), "+f"(c[1]), "+f"(c[2]), "+f"(c[3])
        : "r"(a[0]), "r"(a[1]), "r"(a[2]), "r"(a[3]),
          "r"(b[0]), "r"(b[1]));
}

__device__ __forceinline__ void ldsm_x4(unsigned r[4], const bf16* p)
{
    unsigned addr = (unsigned)__cvta_generic_to_shared(p);
    asm volatile(
        "ldmatrix.sync.aligned.m8n8.x4.shared.b16 {%0,%1,%2,%3}, [%4];\n"
        : "=r"(r[0]), "=r"(r[1]), "=r"(r[2]), "=r"(r[3]) : "r"(addr));
}

__device__ __forceinline__ void ldsm_x4_t(unsigned r[4], const bf16* p)
{
    unsigned addr = (unsigned)__cvta_generic_to_shared(p);
    asm volatile(
        "ldmatrix.sync.aligned.m8n8.x4.trans.shared.b16 {%0,%1,%2,%3}, [%4];\n"
        : "=r"(r[0]), "=r"(r[1]), "=r"(r[2]), "=r"(r[3]) : "r"(addr));
}

// ---------------------------------------------------------------------------
// k-loop bodies
// ---------------------------------------------------------------------------
// Both operands row-major [rows][k] with stride STR; A rows = m, B rows = n.
template<int STR, int KSTEPS>
__device__ __forceinline__ void mma_tile_t(const bf16* TA, const bf16* TB,
                                           float acc[4][4][4],
                                           int wm, int wn, int lane)
{
    const int arow = (lane & 15);
    const int akof = (lane >> 4) << 3;
    const int bcol = (lane & 7) + ((lane >> 4) << 3);
    const int bkof = (lane & 8);

    #pragma unroll
    for (int ks = 0; ks < KSTEPS; ks++) {
        const int kb = ks * 16;
        unsigned af[4][4], bfr[4][2];
        #pragma unroll
        for (int mt = 0; mt < 4; mt++) {
            int row = wm * 64 + mt * 16 + arow;
            ldsm_x4(af[mt], &TA[row * STR + kb + akof]);
        }
        #pragma unroll
        for (int np = 0; np < 2; np++) {
            unsigned r4[4];
            int col = wn * 32 + np * 16 + bcol;
            ldsm_x4(r4, &TB[col * STR + kb + bkof]);
            bfr[np * 2][0]     = r4[0];
            bfr[np * 2][1]     = r4[1];
            bfr[np * 2 + 1][0] = r4[2];
            bfr[np * 2 + 1][1] = r4[3];
        }
        #pragma unroll
        for (int mt = 0; mt < 4; mt++)
            #pragma unroll
            for (int nt = 0; nt < 4; nt++)
                mma_bf16(acc[mt][nt], af[mt], bfr[nt]);
    }
}

// projT: A = x^T via trans-ldsm from X[k][n] tile (stride XSTR); B = W[n-rows][k] normal.
template<int KSTEPS>
__device__ __forceinline__ void mma_tile_Atrans(const bf16* X, const bf16* W,
                                                float acc[4][4][4],
                                                int wm, int wn, int lane)
{
    const int akrow = (lane & 7) + ((lane >> 4) << 3);  // k offset within 16
    const int anoff = (lane & 8);                       // m offset
    const int bcol = (lane & 7) + ((lane >> 4) << 3);
    const int bkof = (lane & 8);

    #pragma unroll
    for (int ks = 0; ks < KSTEPS; ks++) {
        const int kb = ks * 16;
        unsigned af[4][4], bfr[4][2];
        #pragma unroll
        for (int mt = 0; mt < 4; mt++) {
            int nbase = wm * 64 + mt * 16;
            ldsm_x4_t(af[mt], &X[(kb + akrow) * XSTR + nbase + anoff]);
        }
        #pragma unroll
        for (int np = 0; np < 2; np++) {
            unsigned r4[4];
            int col = wn * 32 + np * 16 + bcol;
            ldsm_x4(r4, &W[col * CSTR + kb + bkof]);
            bfr[np * 2][0]     = r4[0];
            bfr[np * 2][1]     = r4[1];
            bfr[np * 2 + 1][0] = r4[2];
            bfr[np * 2 + 1][1] = r4[3];
        }
        #pragma unroll
        for (int mt = 0; mt < 4; mt++)
            #pragma unroll
            for (int nt = 0; nt < 4; nt++)
                mma_bf16(acc[mt][nt], af[mt], bfr[nt]);
    }
}

// projV: A = W[m-rows][k] normal; B = x^T via trans-ldsm from X[k][n] tile.
template<int KSTEPS>
__device__ __forceinline__ void mma_tile_Btrans(const bf16* W, const bf16* X,
                                                float acc[4][4][4],
                                                int wm, int wn, int lane)
{
    const int arow = (lane & 15);
    const int akof = (lane >> 4) << 3;
    const int bkrow = (lane & 15);                 // k offset within 16
    const int bnoff = (lane >> 4) << 3;            // n offset

    #pragma unroll
    for (int ks = 0; ks < KSTEPS; ks++) {
        const int kb = ks * 16;
        unsigned af[4][4], bfr[4][2];
        #pragma unroll
        for (int mt = 0; mt < 4; mt++) {
            int row = wm * 64 + mt * 16 + arow;
            ldsm_x4(af[mt], &W[row * CSTR + kb + akof]);
        }
        #pragma unroll
        for (int np = 0; np < 2; np++) {
            unsigned r4[4];
            int colb = wn * 32 + np * 16;
            ldsm_x4_t(r4, &X[(kb + bkrow) * XSTR + colb + bnoff]);
            bfr[np * 2][0]     = r4[0];
            bfr[np * 2][1]     = r4[1];
            bfr[np * 2 + 1][0] = r4[2];
            bfr[np * 2 + 1][1] = r4[3];
        }
        #pragma unroll
        for (int mt = 0; mt < 4; mt++)
            #pragma unroll
            for (int nt = 0; nt < 4; nt++)
                mma_bf16(acc[mt][nt], af[mt], bfr[nt]);
    }
}

// ---------------------------------------------------------------------------
// staging helpers
// ---------------------------------------------------------------------------
// bf16 rows [row][k-contig], 32-k chunk, stride TSTR (out kernel)
__device__ __forceinline__ void stage_bf16(bf16* T, const bf16* src, size_t gstride,
                                           int k0, int tid)
{
    #pragma unroll
    for (int r = 0; r < 2; r++) {
        int f = tid + r * 256;
        int row = f >> 2, k8 = (f & 3) * 8;
        *reinterpret_cast<uint4*>(&T[row * TSTR + k8]) =
            *reinterpret_cast<const uint4*>(&src[(size_t)row * gstride + k0 + k8]);
    }
}

// fp32 rows, 32-k chunk, stride TSTR (out kernel)
__device__ __forceinline__ void stage_f32(bf16* T, const float* src, size_t gstride,
                                          int k0, int tid)
{
    #pragma unroll
    for (int r = 0; r < 4; r++) {
        int f = tid + r * 256;
        int row = f >> 3, k4 = (f & 7) * 4;
        float4 w4 = *reinterpret_cast<const float4*>(&src[(size_t)row * gstride + k0 + k4]);
        uint2 p;
        p.x = pack2(w4.x, w4.y);
        p.y = pack2(w4.z, w4.w);
        *reinterpret_cast<uint2*>(&T[row * TSTR + k4]) = p;
    }
}

// bf16 rows, 64-k chunk, stride CSTR (scores/ctx)
__device__ __forceinline__ void stage_b64(bf16* T, const bf16* src, size_t gstride,
                                          int k0, int tid)
{
    #pragma unroll
    for (int r = 0; r < 4; r++) {
        int f = tid + r * 256;
        int row = f >> 3, k8 = (f & 7) * 8;
        *reinterpret_cast<uint4*>(&T[row * CSTR + k8]) =
            *reinterpret_cast<const uint4*>(&src[(size_t)row * gstride + k0 + k8]);
    }
}

// fp32 rows -> bf16, 64-k chunk, stride CSTR (proj weights)
__device__ __forceinline__ void stage_w64(bf16* T, const float* src, size_t gstride,
                                          int k0, int tid)
{
    #pragma unroll
    for (int r = 0; r < 8; r++) {
        int f = tid + r * 256;
        int row = f >> 4, k4 = (f & 15) * 4;
        float4 w4 = *reinterpret_cast<const float4*>(&src[(size_t)row * gstride + k0 + k4]);
        uint2 p;
        p.x = pack2(w4.x, w4.y);
        p.y = pack2(w4.z, w4.w);
        *reinterpret_cast<uint2*>(&T[row * CSTR + k4]) = p;
    }
}

// x tile [c][n]: fp32 [64 c][128 n] -> bf16, stride XSTR. Coalesced, no transpose.
__device__ __forceinline__ void stage_x(bf16* T, const float* xb, int k0, int n0, int tid)
{
    #pragma unroll
    for (int r = 0; r < 8; r++) {
        int f = tid + r * 256;
        int row = f >> 5, n4 = (f & 31) * 4;
        float4 v = *reinterpret_cast<const float4*>(&xb[(size_t)(k0 + row) * N_ + n0 + n4]);
        uint2 p;
        p.x = pack2(v.x, v.y);
        p.y = pack2(v.z, v.w);
        *reinterpret_cast<uint2*>(&T[row * XSTR + n4]) = p;
    }
}

// ---------------------------------------------------------------------------
// projT: q/k projection, transposed output. D[n][mid] = sum_c x[c][n] w[mid][c]
// grid (MID/128=2, N/128=16, 2B), 256 thr, dynamic smem.
// ---------------------------------------------------------------------------
struct __align__(16) ProjSmem {
    bf16 X[2][PBK * XSTR];
    bf16 W[2][TBM * CSTR];
};

__global__ __launch_bounds__(256, 2) void projT_mma(
    const float* __restrict__ x,
    const float* __restrict__ wq, const float* __restrict__ bq,
    const float* __restrict__ gq, const float* __restrict__ betaq,
    const float* __restrict__ mq, const float* __restrict__ vq,
    const float* __restrict__ wk, const float* __restrict__ bk,
    const float* __restrict__ gk, const float* __restrict__ betak,
    const float* __restrict__ mk, const float* __restrict__ vk)
{
    extern __shared__ char smem_raw[];
    ProjSmem* sm = reinterpret_cast<ProjSmem*>(smem_raw);

    const int mat = blockIdx.z / B_;
    const int b   = blockIdx.z % B_;
    const int n0  = blockIdx.y * TBM;
    const int c0  = blockIdx.x * TBN;
    const int tid  = threadIdx.x;
    const int lane = tid & 31, wid = tid >> 5;
    const int wm = wid & 1, wn = wid >> 1;
    const int g = lane >> 2, tg = lane & 3;

    const float* w  = (mat == 0) ? wq : wk;
    const float* xb = x + (size_t)b * C_ * N_;

    float acc[4][4][4] = {};

    stage_x(sm->X[0], xb, 0, n0, tid);
    stage_w64(sm->W[0], w + (size_t)c0 * C_, C_, 0, tid);
    __syncthreads();

    for (int k0 = 0; k0 < C_; k0 += PBK) {
        const int buf = (k0 / PBK) & 1;
        if (k0 + PBK < C_) {
            stage_x(sm->X[buf ^ 1], xb, k0 + PBK, n0, tid);
            stage_w64(sm->W[buf ^ 1], w + (size_t)c0 * C_, C_, k0 + PBK, tid);
        }
        mma_tile_Atrans<4>(sm->X[buf], sm->W[buf], acc, wm, wn, lane);
        __syncthreads();
    }

    bf16* dst = (mat == 0) ? g_qT : g_kT;
    const float *gb = (mat == 0) ? gq : gk, *bb = (mat == 0) ? bq : bk;
    const float *mb = (mat == 0) ? mq : mk, *vb2 = (mat == 0) ? vq : vk;
    const float *eb = (mat == 0) ? betaq : betak;

    float sc[4][2], of[4][2];
    #pragma unroll
    for (int nt = 0; nt < 4; nt++) {
        #pragma unroll
        for (int h = 0; h < 2; h++) {
            int ch = c0 + wn * 32 + nt * 8 + 2 * tg + h;
            float inv = gb[ch] * rsqrtf(vb2[ch] + EPS_);
            sc[nt][h] = inv;
            of[nt][h] = (bb[ch] - mb[ch]) * inv + eb[ch];
        }
    }

    #pragma unroll
    for (int mt = 0; mt < 4; mt++) {
        int r0 = n0 + wm * 64 + mt * 16 + g;
        #pragma unroll
        for (int nt = 0; nt < 4; nt++) {
            int col = c0 + wn * 32 + nt * 8 + 2 * tg;
            float v00 = fmaxf(acc[mt][nt][0] * sc[nt][0] + of[nt][0], 0.0f);
            float v01 = fmaxf(acc[mt][nt][1] * sc[nt][1] + of[nt][1], 0.0f);
            float v10 = fmaxf(acc[mt][nt][2] * sc[nt][0] + of[nt][0], 0.0f);
            float v11 = fmaxf(acc[mt][nt][3] * sc[nt][1] + of[nt][1], 0.0f);
            *reinterpret_cast<unsigned*>(&dst[((size_t)b * N_ + r0) * MID_ + col]) = pack2(v00, v01);
            *reinterpret_cast<unsigned*>(&dst[((size_t)b * N_ + r0 + 8) * MID_ + col]) = pack2(v10, v11);
        }
    }
}

// ---------------------------------------------------------------------------
// projV: v projection. D[mid][n] = sum_c w[mid][c] x[c][n]
// grid (N/128=16, MID/128=2, B), 256 thr, dynamic smem.
// ---------------------------------------------------------------------------
__global__ __launch_bounds__(256, 2) void projV_mma(
    const float* __restrict__ x,
    const float* __restrict__ wv, const float* __restrict__ bv)
{
    extern __shared__ char smem_raw[];
    ProjSmem* sm = reinterpret_cast<ProjSmem*>(smem_raw);

    const int b  = blockIdx.z;
    const int m0 = blockIdx.y * TBM;
    const int n0 = blockIdx.x * TBN;
    const int tid  = threadIdx.x;
    const int lane = tid & 31, wid = tid >> 5;
    const int wm = wid & 1, wn = wid >> 1;
    const int g = lane >> 2, tg = lane & 3;

    const float* xb = x + (size_t)b * C_ * N_;

    float acc[4][4][4] = {};

    stage_w64(sm->W[0], wv + (size_t)m0 * C_, C_, 0, tid);
    stage_x(sm->X[0], xb, 0, n0, tid);
    __syncthreads();

    for (int k0 = 0; k0 < C_; k0 += PBK) {
        const int buf = (k0 / PBK) & 1;
        if (k0 + PBK < C_) {
            stage_w64(sm->W[buf ^ 1], wv + (size_t)m0 * C_, C_, k0 + PBK, tid);
            stage_x(sm->X[buf ^ 1], xb, k0 + PBK, n0, tid);
        }
        mma_tile_Btrans<4>(sm->W[buf], sm->X[buf], acc, wm, wn, lane);
        __syncthreads();
    }

    #pragma unroll
    for (int mt = 0; mt < 4; mt++) {
        int r0 = m0 + wm * 64 + mt * 16 + g;
        int r1 = r0 + 8;
        float b0v = bv[r0], b1v = bv[r1];
        #pragma unroll
        for (int nt = 0; nt < 4; nt++) {
            int col = n0 + wn * 32 + nt * 8 + 2 * tg;
            *reinterpret_cast<unsigned*>(&g_v[((size_t)b * MID_ + r0) * N_ + col]) =
                pack2(acc[mt][nt][0] + b0v, acc[mt][nt][1] + b0v);
            *reinterpret_cast<unsigned*>(&g_v[((size_t)b * MID_ + r1) * N_ + col]) =
                pack2(acc[mt][nt][2] + b1v, acc[mt][nt][3] + b1v);
        }
    }
}

// ---------------------------------------------------------------------------
// scores: S^T[j][i] = (1/16) sum_m k[m][j] q[m][i]; epilogue emits partial
// softmax stats per (j, i-block). grid (N/128 i, N/128 j, B), 256 thr.
// ---------------------------------------------------------------------------
struct __align__(16) ScoresSmem {
    bf16 As[2][TBM * CSTR];
    bf16 Bs[2][TBM * CSTR];
    float pmS[TBM][4];
    float psS[TBM][4];
};

__global__ __launch_bounds__(256, 2) void scores_mma()
{
    extern __shared__ char smem_raw[];
    ScoresSmem* sm = reinterpret_cast<ScoresSmem*>(smem_raw);

    const int b    = blockIdx.z;
    const int j0   = blockIdx.y * TBM;
    const int i0   = blockIdx.x * TBN;
    const int iblk = blockIdx.x;
    const int tid  = threadIdx.x;
    const int lane = tid & 31, wid = tid >> 5;
    const int wm = wid & 1, wn = wid >> 1;
    const int g = lane >> 2, tg = lane & 3;

    const bf16* kT = g_kT + ((size_t)b * N_ + j0) * MID_;
    const bf16* qT = g_qT + ((size_t)b * N_ + i0) * MID_;

    float acc[4][4][4] = {};

    stage_b64(sm->As[0], kT, MID_, 0, tid);
    stage_b64(sm->Bs[0], qT, MID_, 0, tid);
    __syncthreads();

    for (int k0 = 0; k0 < MID_; k0 += CBK) {
        const int buf = (k0 / CBK) & 1;
        if (k0 + CBK < MID_) {
            stage_b64(sm->As[buf ^ 1], kT, MID_, k0 + CBK, tid);
            stage_b64(sm->Bs[buf ^ 1], qT, MID_, k0 + CBK, tid);
        }
        mma_tile_t<CSTR, 4>(sm->As[buf], sm->Bs[buf], acc, wm, wn, lane);
        __syncthreads();
    }

    // scale in place, store S^T
    #pragma unroll
    for (int mt = 0; mt < 4; mt++) {
        #pragma unroll
        for (int nt = 0; nt < 4; nt++) {
            acc[mt][nt][0] *= 0.0625f; acc[mt][nt][1] *= 0.0625f;
            acc[mt][nt][2] *= 0.0625f; acc[mt][nt][3] *= 0.0625f;
            int row = j0 + wm * 64 + mt * 16 + g;
            int col = i0 + wn * 32 + nt * 8 + 2 * tg;
            *reinterpret_cast<unsigned*>(&g_sT[((size_t)b * N_ + row) * N_ + col]) =
                pack2(acc[mt][nt][0], acc[mt][nt][1]);
            *reinterpret_cast<unsigned*>(&g_sT[((size_t)b * N_ + row + 8) * N_ + col]) =
                pack2(acc[mt][nt][2], acc[mt][nt][3]);
        }
    }

    // partial softmax stats over this CTA's 128 i-cols
    #pragma unroll
    for (int mt = 0; mt < 4; mt++) {
        float m0 = -3.0e38f, m1 = -3.0e38f;
        #pragma unroll
        for (int nt = 0; nt < 4; nt++) {
            m0 = fmaxf(m0, fmaxf(acc[mt][nt][0], acc[mt][nt][1]));
            m1 = fmaxf(m1, fmaxf(acc[mt][nt][2], acc[mt][nt][3]));
        }
        m0 = fmaxf(m0, __shfl_xor_sync(0xffffffffu, m0, 1));
        m0 = fmaxf(m0, __shfl_xor_sync(0xffffffffu, m0, 2));
        m1 = fmaxf(m1, __shfl_xor_sync(0xffffffffu, m1, 1));
        m1 = fmaxf(m1, __shfl_xor_sync(0xffffffffu, m1, 2));
        if (tg == 0) {
            sm->pmS[wm * 64 + mt * 16 + g][wn] = m0;
            sm->pmS[wm * 64 + mt * 16 + g + 8][wn] = m1;
        }
    }
    __syncthreads();

    #pragma unroll
    for (int mt = 0; mt < 4; mt++) {
        int row0 = wm * 64 + mt * 16 + g, row1 = row0 + 8;
        float TM0 = fmaxf(fmaxf(sm->pmS[row0][0], sm->pmS[row0][1]),
                          fmaxf(sm->pmS[row0][2], sm->pmS[row0][3]));
        float TM1 = fmaxf(fmaxf(sm->pmS[row1][0], sm->pmS[row1][1]),
                          fmaxf(sm->pmS[row1][2], sm->pmS[row1][3]));
        float s0 = 0.0f, s1 = 0.0f;
        #pragma unroll
        for (int nt = 0; nt < 4; nt++) {
            s0 += __expf(acc[mt][nt][0] - TM0) + __expf(acc[mt][nt][1] - TM0);
            s1 += __expf(acc[mt][nt][2] - TM1) + __expf(acc[mt][nt][3] - TM1);
        }
        s0 += __shfl_xor_sync(0xffffffffu, s0, 1);
        s0 += __shfl_xor_sync(0xffffffffu, s0, 2);
        s1 += __shfl_xor_sync(0xffffffffu, s1, 1);
        s1 += __shfl_xor_sync(0xffffffffu, s1, 2);
        if (tg == 0) { sm->psS[row0][wn] = s0; sm->psS[row1][wn] = s1; }
    }
    __syncthreads();

    if (wn == 0 && tg == 0) {
        #pragma unroll
        for (int mt = 0; mt < 4; mt++) {
            #pragma unroll
            for (int h = 0; h < 2; h++) {
                int row = wm * 64 + mt * 16 + g + h * 8;
                float TM = fmaxf(fmaxf(sm->pmS[row][0], sm->pmS[row][1]),
                                 fmaxf(sm->pmS[row][2], sm->pmS[row][3]));
                float S  = sm->psS[row][0] + sm->psS[row][1] + sm->psS[row][2] + sm->psS[row][3];
                size_t idx = ((size_t)b * NIB + iblk) * N_ + j0 + row;
                g_pmax[idx] = TM;
                g_psum[idx] = S;
            }
        }
    }
}

// ---------------------------------------------------------------------------
// colcomb: combine NIB partials per (b, j). grid (N/256, B), 256 thr.
// ---------------------------------------------------------------------------
__global__ __launch_bounds__(256) void colcomb_kernel()
{
    const int j = blockIdx.x * 256 + threadIdx.x;
    const int b = blockIdx.y;
    float M = -3.0e38f, S = 0.0f;
    #pragma unroll
    for (int p = 0; p < NIB; p++) {
        float m2 = g_pmax[((size_t)b * NIB + p) * N_ + j];
        float s2 = g_psum[((size_t)b * NIB + p) * N_ + j];
        float mn = fmaxf(M, m2);
        S = S * __expf(M - mn) + s2 * __expf(m2 - mn);
        M = mn;
    }
    g_cmax[b * N_ + j] = M;
    g_cinv[b * N_ + j] = 1.0f / S;
}

// ---------------------------------------------------------------------------
// ctx: ctx^T[j][c] = sum_i P[i][j] v[c][i], P = exp(S^T[j][i]-cm[j])*ci[j]
// grid (MID/128=2, N/128=16, B), 256 thr, dynamic smem.
// ---------------------------------------------------------------------------
struct __align__(16) CtxSmem {
    bf16 As[2][TBM * CSTR];
    bf16 Bs[2][TBM * CSTR];
    float cm[TBM], ci[TBM];
};

__global__ __launch_bounds__(256, 2) void ctx_mma()
{
    extern __shared__ char smem_raw[];
    CtxSmem* sm = reinterpret_cast<CtxSmem*>(smem_raw);

    const int b  = blockIdx.z;
    const int j0 = blockIdx.y * TBM;
    const int c0 = blockIdx.x * TBN;
    const int tid  = threadIdx.x;
    const int lane = tid & 31, wid = tid >> 5;
    const int wm = wid & 1, wn = wid >> 1;
    const int g = lane >> 2, tg = lane & 3;

    if (tid < TBM) {
        sm->cm[tid] = g_cmax[b * N_ + j0 + tid];
        sm->ci[tid] = g_cinv[b * N_ + j0 + tid];
    }
    __syncthreads();

    const bf16* sT = g_sT + ((size_t)b * N_ + j0) * N_;
    const bf16* vb = g_v + ((size_t)b * MID_ + c0) * N_;

    float acc[4][4][4] = {};

    auto stage_P = [&](bf16* T, int k0) {
        #pragma unroll
        for (int r = 0; r < 4; r++) {
            int f = tid + r * 256;
            int row = f >> 3, i8 = (f & 7) * 8;
            uint4 raw4 = *reinterpret_cast<const uint4*>(&sT[(size_t)row * N_ + k0 + i8]);
            const unsigned u[4] = {raw4.x, raw4.y, raw4.z, raw4.w};
            float cmv = sm->cm[row], civ = sm->ci[row];
            unsigned po[4];
            #pragma unroll
            for (int q = 0; q < 4; q++) {
                float2 fv = __bfloat1622float2(*reinterpret_cast<const bf162*>(&u[q]));
                po[q] = pack2(__expf(fv.x - cmv) * civ, __expf(fv.y - cmv) * civ);
            }
            uint4 o = {po[0], po[1], po[2], po[3]};
            *reinterpret_cast<uint4*>(&T[row * CSTR + i8]) = o;
        }
    };

    stage_P(sm->As[0], 0);
    stage_b64(sm->Bs[0], vb, N_, 0, tid);
    __syncthreads();

    for (int k0 = 0; k0 < N_; k0 += CBK) {
        const int buf = (k0 / CBK) & 1;
        if (k0 + CBK < N_) {
            stage_P(sm->As[buf ^ 1], k0 + CBK);
            stage_b64(sm->Bs[buf ^ 1], vb, N_, k0 + CBK, tid);
        }
        mma_tile_t<CSTR, 4>(sm->As[buf], sm->Bs[buf], acc, wm, wn, lane);
        __syncthreads();
    }

    #pragma unroll
    for (int mt = 0; mt < 4; mt++) {
        int row = j0 + wm * 64 + mt * 16 + g;
        #pragma unroll
        for (int nt = 0; nt < 4; nt++) {
            int col = c0 + wn * 32 + nt * 8 + 2 * tg;
            *reinterpret_cast<unsigned*>(&g_ctxT[((size_t)b * N_ + row) * MID_ + col]) =
                pack2(acc[mt][nt][0], acc[mt][nt][1]);
            *reinterpret_cast<unsigned*>(&g_ctxT[((size_t)b * N_ + row + 8) * MID_ + col]) =
                pack2(acc[mt][nt][2], acc[mt][nt][3]);
        }
    }
}

// ---------------------------------------------------------------------------
// out: out[c'][n] = x + sum_m wo[c'][m] ctx^T[n][m] + bo[c']
// grid (N/128, C/128, B), 256 thr.
// ---------------------------------------------------------------------------
__global__ __launch_bounds__(256, 2) void out_mma(
    const float* __restrict__ x,
    const float* __restrict__ wo,
    const float* __restrict__ bo,
    float* __restrict__ out)
{
    __shared__ __align__(16) bf16 As[2][TBM * TSTR];
    __shared__ __align__(16) bf16 Bs[2][TBM * TSTR];

    const int b  = blockIdx.z;
    const int m0 = blockIdx.y * TBM;
    const int n0 = blockIdx.x * TBN;
    const int tid  = threadIdx.x;
    const int lane = tid & 31, wid = tid >> 5;
    const int wm = wid & 1, wn = wid >> 1;
    const int g = lane >> 2, tg = lane & 3;

    const bf16* cT = g_ctxT + ((size_t)b * N_ + n0) * MID_;

    float acc[4][4][4] = {};

    stage_f32(As[0], wo + (size_t)m0 * MID_, MID_, 0, tid);
    stage_bf16(Bs[0], cT, MID_, 0, tid);
    __syncthreads();

    for (int k0 = 0; k0 < MID_; k0 += TBK) {
        const int buf = (k0 / TBK) & 1;
        if (k0 + TBK < MID_) {
            stage_f32(As[buf ^ 1], wo + (size_t)m0 * MID_, MID_, k0 + TBK, tid);
            stage_bf16(Bs[buf ^ 1], cT, MID_, k0 + TBK, tid);
        }
        mma_tile_t<TSTR, 2>(As[buf], Bs[buf], acc, wm, wn, lane);
        __syncthreads();
    }

    #pragma unroll
    for (int mt = 0; mt < 4; mt++) {
        int r0 = m0 + wm * 64 + mt * 16 + g;
        int r1 = r0 + 8;
        float bo0 = bo[r0], bo1 = bo[r1];
        #pragma unroll
        for (int nt = 0; nt < 4; nt++) {
            int col = n0 + wn * 32 + nt * 8 + 2 * tg;
            size_t a0 = ((size_t)b * C_ + r0) * N_ + col;
            size_t a1 = ((size_t)b * C_ + r1) * N_ + col;
            float2 x0 = *reinterpret_cast<const float2*>(&x[a0]);
            float2 x1 = *reinterpret_cast<const float2*>(&x[a1]);
            float2 v0 = {acc[mt][nt][0] + bo0 + x0.x, acc[mt][nt][1] + bo0 + x0.y};
            float2 v1 = {acc[mt][nt][2] + bo1 + x1.x, acc[mt][nt][3] + bo1 + x1.y};
            *reinterpret_cast<float2*>(&out[a0]) = v0;
            *reinterpret_cast<float2*>(&out[a1]) = v1;
        }
    }
}

// ---------------------------------------------------------------------------
extern "C" void kernel_launch(void* const* d_in, const int* in_sizes, int n_in,
                              void* d_out, int out_size)
{
    (void)in_sizes; (void)n_in; (void)out_size;
    const float* x     = (const float*)d_in[0];
    const float* wq    = (const float*)d_in[1];
    const float* bq    = (const float*)d_in[2];
    const float* gq    = (const float*)d_in[3];
    const float* betaq = (const float*)d_in[4];
    const float* wk    = (const float*)d_in[5];
    const float* bk    = (const float*)d_in[6];
    const float* gk    = (const float*)d_in[7];
    const float* betak = (const float*)d_in[8];
    const float* wv    = (const float*)d_in[9];
    const float* bv    = (const float*)d_in[10];
    const float* wo    = (const float*)d_in[11];
    const float* bo    = (const float*)d_in[12];
    const float* mq    = (const float*)d_in[13];
    const float* vq    = (const float*)d_in[14];
    const float* mk    = (const float*)d_in[15];
    const float* vk    = (const float*)d_in[16];
    float* out = (float*)d_out;

    cudaFuncSetAttribute(projT_mma, cudaFuncAttributeMaxDynamicSharedMemorySize,
                         (int)sizeof(ProjSmem));
    cudaFuncSetAttribute(projV_mma, cudaFuncAttributeMaxDynamicSharedMemorySize,
                         (int)sizeof(ProjSmem));
    cudaFuncSetAttribute(scores_mma, cudaFuncAttributeMaxDynamicSharedMemorySize,
                         (int)sizeof(ScoresSmem));
    cudaFuncSetAttribute(ctx_mma, cudaFuncAttributeMaxDynamicSharedMemorySize,
                         (int)sizeof(CtxSmem));

    dim3 blk(256);
    projT_mma<<<dim3(MID_/TBN, N_/TBM, 2*B_), blk, sizeof(ProjSmem)>>>(
        x, wq, bq, gq, betaq, mq, vq, wk, bk, gk, betak, mk, vk);
    projV_mma<<<dim3(N_/TBN, MID_/TBM, B_), blk, sizeof(ProjSmem)>>>(x, wv, bv);
    scores_mma<<<dim3(N_/TBN, N_/TBM, B_), blk, sizeof(ScoresSmem)>>>();
    colcomb_kernel<<<dim3(N_/256, B_), blk>>>();
    ctx_mma<<<dim3(MID_/TBN, N_/TBM, B_), blk, sizeof(CtxSmem)>>>();
    out_mma<<<dim3(N_/TBN, C_/TBM, B_), blk>>>(x, wo, bo, out);
}